// round 12
// baseline (speedup 1.0000x reference)
#include <cuda_runtime.h>
#include <cuda_fp16.h>
#include <cstdint>

#define HID   1024
#define TS1   1001            // TYPE_SIZE + 1 embedding rows
#define MPAD  1024            // padded M (16 tiles of 64)
#define BATCH 32
#define SEQ   512
#define NTOK  (BATCH * SEQ)
#define NG    5               // used gates: gi, gz, go, gib, gd
#define NP    (NG * HID)      // 5120
#define WROW  2048            // W_rec row stride (2H)
#define KK    1024            // K (single-pass fp16)

// ---------------- device-global scratch (no allocs allowed) ----------------
__device__ __half g_A[MPAD * KK];            // 2 MB
__device__ __half g_B[NP * KK];              // 10 MB  slab g: 0=gi,1=gz,2=go,3=gib,4=gd
__device__ float g_table[TS1 * 4 * HID];     // 16.4 MB {c, c_bar, sig(go), sp(gd)}

__constant__ int c_chunk[NG] = {0, 2, 3, 4, 6};   // gi, gz, go, gib, gd

// ---------------- base-target PTX helpers ----------------
__device__ __forceinline__ uint32_t smem_u32(const void* p) {
    uint32_t a;
    asm("{ .reg .u64 t; cvta.to.shared.u64 t, %1; cvt.u32.u64 %0, t; }"
        : "=r"(a) : "l"(p));
    return a;
}
#define CP_ASYNC16(dst, src) \
    asm volatile("cp.async.cg.shared.global [%0], [%1], 16;" \
                 :: "r"(dst), "l"(src))
#define CP_COMMIT() asm volatile("cp.async.commit_group;" ::: "memory")
#define CP_WAIT0()  asm volatile("cp.async.wait_group 0;" ::: "memory")
#define CP_WAIT1()  asm volatile("cp.async.wait_group 1;" ::: "memory")

__device__ __forceinline__ void ldsm_x4(uint32_t* r, uint32_t addr) {
    asm volatile("ldmatrix.sync.aligned.m8n8.x4.shared.b16 {%0,%1,%2,%3}, [%4];"
        : "=r"(r[0]), "=r"(r[1]), "=r"(r[2]), "=r"(r[3]) : "r"(addr));
}
__device__ __forceinline__ void mma_f16(float* c, const uint32_t* a,
                                        uint32_t b0, uint32_t b1) {
    asm volatile(
        "mma.sync.aligned.m16n8k16.row.col.f32.f16.f16.f32 "
        "{%0,%1,%2,%3}, {%4,%5,%6,%7}, {%8,%9}, {%0,%1,%2,%3};"
        : "+f"(c[0]), "+f"(c[1]), "+f"(c[2]), "+f"(c[3])
        : "r"(a[0]), "r"(a[1]), "r"(a[2]), "r"(a[3]), "r"(b0), "r"(b1));
}

// ---- fast transcendentals (MUFU) ----
#define LOG2E 1.4426950408889634f
#define LN2   0.6931471805599453f
__device__ __forceinline__ float ex2f(float x) {
    float y; asm("ex2.approx.f32 %0, %1;" : "=f"(y) : "f"(x)); return y;
}
__device__ __forceinline__ float lg2f(float x) {
    float y; asm("lg2.approx.f32 %0, %1;" : "=f"(y) : "f"(x)); return y;
}
__device__ __forceinline__ float rcpf(float x) {
    float y; asm("rcp.approx.f32 %0, %1;" : "=f"(y) : "f"(x)); return y;
}
__device__ __forceinline__ float fsigmoid(float x){ return rcpf(1.f + ex2f(-x * LOG2E)); }
__device__ __forceinline__ float fsoftplus(float x) {
    float e = ex2f(-fabsf(x) * LOG2E);
    return fmaxf(x, 0.f) + LN2 * lg2f(1.f + e);
}

// ---------------------------------------------------------------------------
// Merged conversion kernel: A then B region in one launch
// ---------------------------------------------------------------------------
#define CONV_TOT (MPAD * HID + NP * HID)

__global__ __launch_bounds__(256)
void conv_AB(const float* __restrict__ emb, const float* __restrict__ W) {
    int idx = blockIdx.x * 256 + threadIdx.x;
    if (idx < MPAD * HID) {
        int e = idx >> 10;
        float a = (e < TS1) ? emb[idx] : 0.f;
        g_A[idx] = __float2half_rn(a);
    } else {
        int j = idx - MPAD * HID;
        if (j < NP * HID) {
            int n = j >> 10, k = j & 1023;
            int c = n >> 10, h = n & 1023;
            float a = W[(size_t)(c_chunk[c] * HID + h) * WROW + k];
            g_B[j] = __float2half_rn(a);
        }
    }
}

// ---------------------------------------------------------------------------
// Shared gemm skeleton pieces (macro-free, written out per kernel).
// Block 64e x 64h; warps 2(m) x 4(n). BK=32, 3 stages, 1 barrier/iter.
// ---------------------------------------------------------------------------
#define BK      32
#define KT      (KK / BK)                 // 32
#define TILE_B  (64 * 80)                 // 5120 B per 64-row tile per stage

// ======================= gemm3: gi, gz, gib -> c, c_bar =====================
#define NG3      3
#define STG_B3   ((NG3 + 1) * TILE_B)     // 20480 B per stage
#define SMEM_SZ3 (3 * STG_B3)             // 61440 B ; x3 CTAs = 184320 <= 228KB

__global__ __launch_bounds__(256, 3)
void gemm3(const float* __restrict__ brec) {
    extern __shared__ __align__(16) char smem[];
    const uint32_t sbase = smem_u32(smem);

    const int tid = threadIdx.x;
    const int wid = tid >> 5, lane = tid & 31;
    const int bh = blockIdx.x * 64;
    const int bm = blockIdx.y * 64;
    const int wm = (wid & 1) * 32;
    const int wn = (wid >> 1) * 16;

    const __half* gA = g_A + (size_t)bm * KK;
    const __half* gB = g_B + (size_t)bh * KK;

    const int lrow = tid >> 2, lch = tid & 3;

    auto issue = [&](int kt, int s) {
        const int k0 = kt * BK;
        const uint32_t st = sbase + s * STG_B3;
        const uint32_t doff = lrow * 80 + lch * 16;
        const size_t   soff = (size_t)lrow * KK + k0 + lch * 8;
        CP_ASYNC16(st + doff, gA + soff);
        CP_ASYNC16(st + 1 * TILE_B + doff, gB + (size_t)0 * HID * KK + soff); // gi
        CP_ASYNC16(st + 2 * TILE_B + doff, gB + (size_t)1 * HID * KK + soff); // gz
        CP_ASYNC16(st + 3 * TILE_B + doff, gB + (size_t)3 * HID * KK + soff); // gib
    };

    float acc[NG3][4][4];
#pragma unroll
    for (int g = 0; g < NG3; g++)
#pragma unroll
        for (int j = 0; j < 4; j++)
#pragma unroll
            for (int v = 0; v < 4; v++) acc[g][j][v] = 0.f;

    issue(0, 0); CP_COMMIT();
    issue(1, 1); CP_COMMIT();

    const uint32_t lmoff = (lane & 15) * 80 + (lane >> 4) * 16;

    int s = 0;
    for (int kt = 0; kt < KT; kt++) {
        if (kt < KT - 1) CP_WAIT1(); else CP_WAIT0();
        __syncthreads();

        const uint32_t aBase = sbase + s * STG_B3;

#pragma unroll
        for (int ks = 0; ks < 2; ks++) {
            uint32_t af[2][4];
            ldsm_x4(af[0], aBase + (wm +  0) * 80 + ks * 32 + lmoff);
            ldsm_x4(af[1], aBase + (wm + 16) * 80 + ks * 32 + lmoff);
            if (ks == 0 && kt + 2 < KT) {
                int s2 = s + 2; if (s2 >= 3) s2 -= 3;
                issue(kt + 2, s2);
                CP_COMMIT();
            }
#pragma unroll
            for (int g = 0; g < NG3; g++) {
                uint32_t bf[4];
                ldsm_x4(bf, aBase + (g + 1) * TILE_B + wn * 80 + ks * 32 + lmoff);
                mma_f16(acc[g][0], af[0], bf[0], bf[2]);
                mma_f16(acc[g][1], af[0], bf[1], bf[3]);
                mma_f16(acc[g][2], af[1], bf[0], bf[2]);
                mma_f16(acc[g][3], af[1], bf[1], bf[3]);
            }
        }
        if (++s == 3) s = 0;
    }

    // ---- epilogue: c = sig(gi)*tanh(gz), c_bar = sig(gib)*tanh(gz) ----
    const int cm = lane >> 2, cn = (lane & 3) * 2;

#pragma unroll
    for (int mf = 0; mf < 2; mf++) {
#pragma unroll
        for (int nf = 0; nf < 2; nf++) {
            const int j = mf * 2 + nf;
            const int col = bh + wn + nf * 8 + cn;
            const float2 bgi = *reinterpret_cast<const float2*>(brec + 0 * HID + col);
            const float2 bgz = *reinterpret_cast<const float2*>(brec + 2 * HID + col);
            const float2 bgb = *reinterpret_cast<const float2*>(brec + 4 * HID + col);
#pragma unroll
            for (int half = 0; half < 2; half++) {
                const int e = bm + wm + mf * 16 + cm + half * 8;
                if (e >= TS1) continue;
                const int v = half * 2;
                float gi0 = acc[0][j][v] + bgi.x, gi1 = acc[0][j][v + 1] + bgi.y;
                float gz0 = acc[1][j][v] + bgz.x, gz1 = acc[1][j][v + 1] + bgz.y;
                float gb0 = acc[2][j][v] + bgb.x, gb1 = acc[2][j][v + 1] + bgb.y;

                float tz0 = tanhf(gz0), tz1 = tanhf(gz1);
                float* T = g_table + (size_t)e * (4 * HID) + col;
                *reinterpret_cast<float2*>(T + 0 * HID) =
                    make_float2(fsigmoid(gi0) * tz0, fsigmoid(gi1) * tz1);
                *reinterpret_cast<float2*>(T + 1 * HID) =
                    make_float2(fsigmoid(gb0) * tz0, fsigmoid(gb1) * tz1);
            }
        }
    }
}

// ======================= gemm2: go, gd -> sig(go), sp(gd) ===================
#define NG2      2
#define STG_B2   ((NG2 + 1) * TILE_B)     // 15360 B per stage
#define SMEM_SZ2 (3 * STG_B2)             // 46080 B ; x4 CTAs = 184320 <= 228KB

__global__ __launch_bounds__(256, 4)
void gemm2(const float* __restrict__ brec) {
    extern __shared__ __align__(16) char smem[];
    const uint32_t sbase = smem_u32(smem);

    const int tid = threadIdx.x;
    const int wid = tid >> 5, lane = tid & 31;
    const int bh = blockIdx.x * 64;
    const int bm = blockIdx.y * 64;
    const int wm = (wid & 1) * 32;
    const int wn = (wid >> 1) * 16;

    const __half* gA = g_A + (size_t)bm * KK;
    const __half* gB = g_B + (size_t)bh * KK;

    const int lrow = tid >> 2, lch = tid & 3;

    auto issue = [&](int kt, int s) {
        const int k0 = kt * BK;
        const uint32_t st = sbase + s * STG_B2;
        const uint32_t doff = lrow * 80 + lch * 16;
        const size_t   soff = (size_t)lrow * KK + k0 + lch * 8;
        CP_ASYNC16(st + doff, gA + soff);
        CP_ASYNC16(st + 1 * TILE_B + doff, gB + (size_t)2 * HID * KK + soff); // go
        CP_ASYNC16(st + 2 * TILE_B + doff, gB + (size_t)4 * HID * KK + soff); // gd
    };

    float acc[NG2][4][4];
#pragma unroll
    for (int g = 0; g < NG2; g++)
#pragma unroll
        for (int j = 0; j < 4; j++)
#pragma unroll
            for (int v = 0; v < 4; v++) acc[g][j][v] = 0.f;

    issue(0, 0); CP_COMMIT();
    issue(1, 1); CP_COMMIT();

    const uint32_t lmoff = (lane & 15) * 80 + (lane >> 4) * 16;

    int s = 0;
    for (int kt = 0; kt < KT; kt++) {
        if (kt < KT - 1) CP_WAIT1(); else CP_WAIT0();
        __syncthreads();

        const uint32_t aBase = sbase + s * STG_B2;

#pragma unroll
        for (int ks = 0; ks < 2; ks++) {
            uint32_t af[2][4];
            ldsm_x4(af[0], aBase + (wm +  0) * 80 + ks * 32 + lmoff);
            ldsm_x4(af[1], aBase + (wm + 16) * 80 + ks * 32 + lmoff);
            if (ks == 0 && kt + 2 < KT) {
                int s2 = s + 2; if (s2 >= 3) s2 -= 3;
                issue(kt + 2, s2);
                CP_COMMIT();
            }
#pragma unroll
            for (int g = 0; g < NG2; g++) {
                uint32_t bf[4];
                ldsm_x4(bf, aBase + (g + 1) * TILE_B + wn * 80 + ks * 32 + lmoff);
                mma_f16(acc[g][0], af[0], bf[0], bf[2]);
                mma_f16(acc[g][1], af[0], bf[1], bf[3]);
                mma_f16(acc[g][2], af[1], bf[0], bf[2]);
                mma_f16(acc[g][3], af[1], bf[1], bf[3]);
            }
        }
        if (++s == 3) s = 0;
    }

    // ---- epilogue: sig(go), softplus(gd) ----
    const int cm = lane >> 2, cn = (lane & 3) * 2;

#pragma unroll
    for (int mf = 0; mf < 2; mf++) {
#pragma unroll
        for (int nf = 0; nf < 2; nf++) {
            const int j = mf * 2 + nf;
            const int col = bh + wn + nf * 8 + cn;
            const float2 bgo = *reinterpret_cast<const float2*>(brec + 3 * HID + col);
            const float2 bgd = *reinterpret_cast<const float2*>(brec + 6 * HID + col);
#pragma unroll
            for (int half = 0; half < 2; half++) {
                const int e = bm + wm + mf * 16 + cm + half * 8;
                if (e >= TS1) continue;
                const int v = half * 2;
                float go0 = acc[0][j][v] + bgo.x, go1 = acc[0][j][v + 1] + bgo.y;
                float gd0 = acc[1][j][v] + bgd.x, gd1 = acc[1][j][v + 1] + bgd.y;

                float* T = g_table + (size_t)e * (4 * HID) + col;
                *reinterpret_cast<float2*>(T + 2 * HID) =
                    make_float2(fsigmoid(go0), fsigmoid(go1));
                *reinterpret_cast<float2*>(T + 3 * HID) =
                    make_float2(fsoftplus(gd0), fsoftplus(gd1));
            }
        }
    }
}

// ---------------------------------------------------------------------------
// Token kernel: per-token gather + decay + write 5 outputs [5, T, B, H]
// ---------------------------------------------------------------------------
__global__ __launch_bounds__(256)
void token_kernel(const int* __restrict__ ev, const float* __restrict__ dur,
                  float* __restrict__ out) {
    const int tok = blockIdx.x;        // = t*BATCH + b (matches output layout)
    const int t = tok >> 5;
    const int b = tok & 31;

    const int   e = ev[b * SEQ + t];   // inputs are [B, T]
    const float d = dur[b * SEQ + t];
    const float dl = -d * LOG2E;       // exp(-gd*d) = ex2(gd * dl)

    const float* T = g_table + (size_t)e * (4 * HID);
    const int h = threadIdx.x * 4;

    float4 c  = *reinterpret_cast<const float4*>(T + 0 * HID + h);
    float4 cb = *reinterpret_cast<const float4*>(T + 1 * HID + h);
    float4 go = *reinterpret_cast<const float4*>(T + 2 * HID + h);
    float4 gd = *reinterpret_cast<const float4*>(T + 3 * HID + h);

    float4 hd;
    hd.x = go.x * tanhf(cb.x + (c.x - cb.x) * ex2f(gd.x * dl));
    hd.y = go.y * tanhf(cb.y + (c.y - cb.y) * ex2f(gd.y * dl));
    hd.z = go.z * tanhf(cb.z + (c.z - cb.z) * ex2f(gd.z * dl));
    hd.w = go.w * tanhf(cb.w + (c.w - cb.w) * ex2f(gd.w * dl));

    const size_t stride = (size_t)SEQ * BATCH * HID;
    float* base = out + (size_t)tok * HID + h;

    __stcs(reinterpret_cast<float4*>(base + 0 * stride), hd);
    __stcs(reinterpret_cast<float4*>(base + 1 * stride), c);
    __stcs(reinterpret_cast<float4*>(base + 2 * stride), cb);
    __stcs(reinterpret_cast<float4*>(base + 3 * stride), go);
    __stcs(reinterpret_cast<float4*>(base + 4 * stride), gd);
}

// ---------------------------------------------------------------------------
extern "C" void kernel_launch(void* const* d_in, const int* in_sizes, int n_in,
                              void* d_out, int out_size) {
    const int*   ev  = (const int*)  d_in[0];   // event_seqs   [32, 512] int32
    const float* dur = (const float*)d_in[1];   // duration_seqs[32, 512]
    const float* emb = (const float*)d_in[2];   // emb_table [1001, 1024]
    const float* W   = (const float*)d_in[3];   // W_rec [7168, 2048]
    const float* br  = (const float*)d_in[4];   // b_rec [7168]
    float* out = (float*)d_out;                 // [5, 512, 32, 1024]

    static bool init_done = false;
    if (!init_done) {
        cudaFuncSetAttribute(gemm3, cudaFuncAttributeMaxDynamicSharedMemorySize,
                             SMEM_SZ3);
        cudaFuncSetAttribute(gemm2, cudaFuncAttributeMaxDynamicSharedMemorySize,
                             SMEM_SZ2);
        init_done = true;
    }

    conv_AB<<<(CONV_TOT + 255) / 256, 256>>>(emb, W);

    dim3 g1(HID / 64, MPAD / 64);               // (16, 16) = 256 blocks
    gemm3<<<g1, 256, SMEM_SZ3>>>(br);
    gemm2<<<g1, 256, SMEM_SZ2>>>(br);

    token_kernel<<<NTOK, 256>>>(ev, dur, out);
}